// round 13
// baseline (speedup 1.0000x reference)
#include <cuda_runtime.h>
#include <math.h>
#include <stdint.h>

// ---------------------------------------------------------------------------
// VQ-VAE forward, fp32 direct kernels.
// Output layout (concatenated, float32): out | z | e_k | ids
// ---------------------------------------------------------------------------

static const size_t OUT_OFF = 0;
static const size_t Z_OFF   = (size_t)32 * 3 * 256 * 256;
static const size_t EK_OFF  = Z_OFF + (size_t)32 * 256 * 32 * 32;
static const size_t IDS_OFF = EK_OFF + (size_t)32 * 256 * 32 * 32;

__device__ __align__(16) float g_bufA[(size_t)32 * 64 * 128 * 128];
__device__ __align__(16) float g_bufB[(size_t)32 * 128 * 64 * 64];
__device__ __align__(16) float g_ct[256 * 1024];     // codebook^T [d][code]
__device__ __align__(16) double g_cnorm_d[1024];     // exact norms (phase A keys)
__device__ __align__(16) float g_cnorm_f[1024];      // XLA-warp-order fp32 norms
__device__ int g_ids[32 * 1024];
__device__ int g_nflag;
__device__ int g_flagrows[16384];

#define POS_INF_F __int_as_float(0x7f800000)

// ---------------------------------------------------------------------------
// Conv2d k=3 s=2 p=1, NCHW, optional ReLU.
// Accumulation order (R12): single accumulator, pure (kh, kw, ci) ascending —
// the reduction order of a cudnn/XLA NHWC implicit-GEMM conv. Skipping
// out-of-bounds taps is bit-exact (adding a 0 product is the identity).
// ---------------------------------------------------------------------------
template <int CIN, int COUT, int HIN, int COB, int TH, int TW, bool RELU>
__global__ void __launch_bounds__(128) conv_s2(const float* __restrict__ in,
                                               const float* __restrict__ w,
                                               float* __restrict__ out) {
    constexpr int HOUT = HIN / 2;
    constexpr int WOUT = HIN / 2;
    __shared__ float ws[COB * CIN * 9];

    const int n   = blockIdx.y;
    const int cob = blockIdx.z * COB;
    const int tid = threadIdx.x;
    const int ty  = tid / TW;
    const int tx  = tid % TW;
    const int oh  = blockIdx.x * TH + ty;
    const int ow  = tx;

    const float* inB = in + (size_t)n * CIN * HIN * HIN;

    for (int i = tid; i < COB * CIN * 9; i += TH * TW)
        ws[i] = w[(size_t)(cob + i / (CIN * 9)) * CIN * 9 + (i % (CIN * 9))];
    __syncthreads();

    float acc[COB];
#pragma unroll
    for (int i = 0; i < COB; i++) acc[i] = 0.f;

#pragma unroll
    for (int kh = 0; kh < 3; kh++) {
        int ih = 2 * oh - 1 + kh;
        if ((unsigned)ih >= (unsigned)HIN) continue;
#pragma unroll
        for (int kw = 0; kw < 3; kw++) {
            int iw = 2 * ow - 1 + kw;
            if ((unsigned)iw >= (unsigned)HIN) continue;
            const int k = kh * 3 + kw;
            const float* bp = inB + (size_t)ih * HIN + iw;
#pragma unroll 4
            for (int ci = 0; ci < CIN; ci++) {
                float xv = __ldg(bp + (size_t)ci * HIN * HIN);
#pragma unroll
                for (int co = 0; co < COB; co++)
                    acc[co] = fmaf(xv, ws[(co * CIN + ci) * 9 + k], acc[co]);
            }
        }
    }

    float* o = out + ((size_t)n * COUT + cob) * HOUT * WOUT + (size_t)oh * WOUT + ow;
#pragma unroll
    for (int co = 0; co < COB; co++) {
        float v = acc[co];
        if (RELU) v = fmaxf(v, 0.f);
        o[(size_t)co * HOUT * WOUT] = v;
    }
}

// ---------------------------------------------------------------------------
// ConvTranspose2d k=3 s=2 p=1 outpad=1; ACT: 0 = relu, 1 = sigmoid.
// (Decoder precision does not affect ids.)
// ---------------------------------------------------------------------------
template <int CIN, int COUT, int HIN, int COB, int TH, int TW, int CISTEP, int ACT>
__global__ void __launch_bounds__(128) deconv_s2(const float* __restrict__ in,
                                                 const float* __restrict__ w,
                                                 float* __restrict__ out) {
    constexpr int HOUT = HIN * 2;
    __shared__ float ws[COB * CISTEP * 9];

    const int n   = blockIdx.y;
    const int cob = blockIdx.z * COB;
    const int tid = threadIdx.x;
    const int ty  = tid / TW;
    const int tx  = tid % TW;
    const int a   = blockIdx.x * TH + ty;
    const int b   = tx;

    const float* inB = in + (size_t)n * CIN * HIN * HIN;

    float acc[COB][4];
#pragma unroll
    for (int i = 0; i < COB; i++)
#pragma unroll
        for (int q = 0; q < 4; q++) acc[i][q] = 0.f;

    const bool bOK = (b + 1 < HIN);
    const bool aOK = (a + 1 < HIN);

    for (int ci0 = 0; ci0 < CIN; ci0 += CISTEP) {
        __syncthreads();
        for (int i = tid; i < COB * CISTEP * 9; i += TH * TW) {
            int co = i / (CISTEP * 9);
            int r  = i % (CISTEP * 9);
            int ci = r / 9;
            int k  = r % 9;
            ws[i] = w[(size_t)(cob + co) * CIN * 9 + (size_t)(ci0 + ci) * 9 + k];
        }
        __syncthreads();

#pragma unroll
        for (int ci = 0; ci < CISTEP; ci++) {
            const float* p = inB + (size_t)(ci0 + ci) * HIN * HIN + (size_t)a * HIN + b;
            float v00 = __ldg(p);
            float v01 = bOK ? __ldg(p + 1) : 0.f;
            float v10 = aOK ? __ldg(p + HIN) : 0.f;
            float v11 = (aOK && bOK) ? __ldg(p + HIN + 1) : 0.f;
#pragma unroll
            for (int co = 0; co < COB; co++) {
                const float* wr = &ws[(co * CISTEP + ci) * 9];
                acc[co][0] = fmaf(v00, wr[4], acc[co][0]);
                acc[co][1] = fmaf(v00, wr[3], fmaf(v01, wr[5], acc[co][1]));
                acc[co][2] = fmaf(v00, wr[1], fmaf(v10, wr[7], acc[co][2]));
                acc[co][3] = fmaf(v00, wr[0],
                             fmaf(v01, wr[2],
                             fmaf(v10, wr[6],
                             fmaf(v11, wr[8], acc[co][3]))));
            }
        }
    }

#pragma unroll
    for (int co = 0; co < COB; co++) {
        float r0, r1, r2, r3;
        if (ACT == 0) {
            r0 = fmaxf(acc[co][0], 0.f);
            r1 = fmaxf(acc[co][1], 0.f);
            r2 = fmaxf(acc[co][2], 0.f);
            r3 = fmaxf(acc[co][3], 0.f);
        } else {
            r0 = 1.f / (1.f + expf(-acc[co][0]));
            r1 = 1.f / (1.f + expf(-acc[co][1]));
            r2 = 1.f / (1.f + expf(-acc[co][2]));
            r3 = 1.f / (1.f + expf(-acc[co][3]));
        }
        float* o = out + ((size_t)n * COUT + cob + co) * HOUT * HOUT +
                   (size_t)(2 * a) * HOUT + 2 * b;
        *reinterpret_cast<float2*>(o)        = make_float2(r0, r1);
        *reinterpret_cast<float2*>(o + HOUT) = make_float2(r2, r3);
    }
}

// ---------------------------------------------------------------------------
// XLA GPU row-reduction emulation for 256 elements:
// lane l sums elements l, l+32, ..., l+224 sequentially, then a shfl-down
// tree (+16,+8,+4,+2,+1). Returns the lane-0 value. f(i) = element i.
// ---------------------------------------------------------------------------
template <typename F>
__device__ __forceinline__ float xla_reduce256(F f) {
    float v[32];
#pragma unroll
    for (int l = 0; l < 32; l++) {
        float s = f(l);
#pragma unroll
        for (int i = 1; i < 8; i++) s = __fadd_rn(s, f(l + 32 * i));
        v[l] = s;
    }
    for (int off = 16; off; off >>= 1)
        for (int l = 0; l < off; l++) v[l] = __fadd_rn(v[l], v[l + off]);
    return v[0];
}

// ---------------------------------------------------------------------------
// Codebook prep: transpose + exact fp64 norms (phase A) + XLA-warp-order fp32
// norms (phase B emulation of jnp.sum(cb*cb, axis=1)).
// ---------------------------------------------------------------------------
__global__ void cb_t_kernel(const float* __restrict__ cb) {
    int i = blockIdx.x * 256 + threadIdx.x;
    int d = i >> 10;
    int c = i & 1023;
    g_ct[i] = cb[(size_t)c * 256 + d];
}

__global__ void cb_norm_kernel(const float* __restrict__ cb) {
    int code = blockIdx.x * blockDim.x + threadIdx.x;   // 1024 threads
    if (code >= 1024) return;
    const float* r = cb + (size_t)code * 256;
    double sd = 0.0;
    for (int d = 0; d < 256; d++) {
        float v = r[d];
        sd = fma((double)v, (double)v, sd);
    }
    g_cnorm_d[code] = sd;
    g_cnorm_f[code] = xla_reduce256([&](int i) { return __fmul_rn(r[i], r[i]); });
}

__global__ void reset_flags_kernel() {
    if (threadIdx.x == 0) g_nflag = 0;
}

// merge sorted pairs (b1<=b2),(o1<=o2) -> top2
__device__ __forceinline__ void top2_merge(long long& b1, long long& b2,
                                           long long o1, long long o2) {
    if (o1 < b1) {
        b2 = (b1 < o2) ? b1 : o2;
        b1 = o1;
    } else {
        b2 = (b2 < o1) ? b2 : o1;
    }
}

// ---------------------------------------------------------------------------
// VQ phase A: fast fp32 GEMM + integer-key argmin on the ulp(znorm) grid.
// Flags near-tie rows (key margin <= 24) and binade-edge rows for phase B.
// ---------------------------------------------------------------------------
__global__ void __launch_bounds__(128) vq_kernel(const float* __restrict__ z,
                                                 float* __restrict__ ids_f) {
    constexpr int V = 16;
    constexpr long long LLMAX = 0x7fffffffffffffffLL;
    __shared__ float zs[256 * V];
    __shared__ double invu_s[V];
    __shared__ int   bflag_s[V];
    __shared__ long long red1[4 * V];
    __shared__ long long red2[4 * V];

    const int tid = threadIdx.x;
    const int blk = blockIdx.x;          // 2048 blocks
    const int n   = blk >> 6;
    const int hw0 = (blk & 63) * V;
    const float* zb = z + (size_t)n * 256 * 1024 + hw0;

    for (int i = tid; i < V * 256; i += 128) {
        int v = i & 15;
        int d = i >> 4;
        zs[(d << 4) + v] = zb[(size_t)d * 1024 + v];
    }
    __syncthreads();

    if (tid < V) {
        float s = 0.f;
        for (int d = 0; d < 256; d++) {
            float zd = zs[(d << 4) + tid];
            s = __fadd_rn(s, __fmul_rn(zd, zd));
        }
        int e;
        frexpf(s, &e);              // s in [2^(e-1), 2^e), u = 2^(e-24)
        invu_s[tid] = ldexp(1.0, 24 - e);
        float lo = ldexpf(1.0f, e - 1);
        float hi = ldexpf(1.0f, e);
        bflag_s[tid] = ((s - lo) < 0.006f * s) || ((hi - s) < 3e-5f * hi);
    }
    __syncthreads();

    float acc[V][8];
#pragma unroll
    for (int v = 0; v < V; v++)
#pragma unroll
        for (int j = 0; j < 8; j++) acc[v][j] = 0.f;

    const float4* ctp = reinterpret_cast<const float4*>(g_ct) + tid * 2;
#pragma unroll 2
    for (int d = 0; d < 256; d++) {
        float4 c0 = __ldg(ctp + (size_t)d * 256);
        float4 c1 = __ldg(ctp + (size_t)d * 256 + 1);
        float cv[8] = {c0.x, c0.y, c0.z, c0.w, c1.x, c1.y, c1.z, c1.w};
#pragma unroll
        for (int v = 0; v < V; v++) {
            float zd = zs[(d << 4) + v];
#pragma unroll
            for (int j = 0; j < 8; j++) acc[v][j] = fmaf(zd, cv[j], acc[v][j]);
        }
    }

    double cnd[8];
#pragma unroll
    for (int j = 0; j < 8; j++) cnd[j] = g_cnorm_d[tid * 8 + j];

    const int lane = tid & 31;
    const int warp = tid >> 5;

#pragma unroll
    for (int v = 0; v < V; v++) {
        double invu = invu_s[v];
        long long b1 = LLMAX, b2 = LLMAX;
#pragma unroll
        for (int j = 0; j < 8; j++) {
            double p = 2.0 * (double)acc[v][j];
            long long key = llrint(cnd[j] * invu) - llrint(p * invu);
            long long pk = (key << 10) | (long long)(tid * 8 + j);
            if (pk < b1) { b2 = b1; b1 = pk; }
            else if (pk < b2) { b2 = pk; }
        }
#pragma unroll
        for (int off = 16; off; off >>= 1) {
            long long o1 = __shfl_xor_sync(0xffffffffu, b1, off);
            long long o2 = __shfl_xor_sync(0xffffffffu, b2, off);
            top2_merge(b1, b2, o1, o2);
        }
        if (lane == 0) { red1[warp * V + v] = b1; red2[warp * V + v] = b2; }
    }
    __syncthreads();

    if (tid < V) {
        long long b1 = red1[tid], b2 = red2[tid];
#pragma unroll
        for (int w = 1; w < 4; w++) top2_merge(b1, b2, red1[w * V + tid], red2[w * V + tid]);
        int id  = (int)(b1 & 1023);
        int row = n * 1024 + hw0 + tid;
        g_ids[row] = id;
        ids_f[row] = (float)id;
        long long margin = (b2 >> 10) - (b1 >> 10);
        if (margin <= 24 || bflag_s[tid]) {
            int slot = atomicAdd(&g_nflag, 1);
            if (slot < 16384) g_flagrows[slot] = row;
        }
    }
}

// ---------------------------------------------------------------------------
// VQ phase B: structural emulation of the reference for flagged rows.
//   znorm : XLA warp-reduction order (strided-32 + shfl tree)
//   m'_j  : sequential ascending-k fp32 fma(2z,c)  (cublas-like)
//   cn_j  : XLA warp-reduction order (precomputed)
//   d_j   : fl( fl(znorm - m') + cn )  in real fp32 arithmetic
// argmin, ties -> lowest index.
// ---------------------------------------------------------------------------
__global__ void __launch_bounds__(256) vq_fix_kernel(const float* __restrict__ z,
                                                     float* __restrict__ ids_f) {
    int nf = g_nflag;
    if (nf > 16384) nf = 16384;
    if ((int)blockIdx.x >= nf) return;
    const int row = g_flagrows[blockIdx.x];
    const int n = row >> 10;
    const int hw = row & 1023;
    const int t = threadIdx.x;

    __shared__ float zsh[256];
    __shared__ float znf_sh;
    __shared__ unsigned long long redp[8];

    zsh[t] = z[((size_t)n * 256 + t) * 1024 + hw];
    __syncthreads();

    if (t == 0) {
        znf_sh = xla_reduce256([&](int i) { return __fmul_rn(zsh[i], zsh[i]); });
    }
    __syncthreads();
    const float znf = znf_sh;

    unsigned long long best = 0xffffffffffffffffULL;
#pragma unroll
    for (int q = 0; q < 4; q++) {
        int j = t + 256 * q;
        float a = 0.f;
        for (int d = 0; d < 256; d++)
            a = fmaf(2.0f * zsh[d], g_ct[d * 1024 + j], a);   // seq ascending-k
        float s1 = __fadd_rn(znf, -a);                        // fl(znorm - 2m)
        float dj = __fadd_rn(s1, g_cnorm_f[j]);               // fl(... + cn)
        unsigned bb  = __float_as_uint(dj);
        unsigned key = (bb & 0x80000000u) ? ~bb : (bb | 0x80000000u);
        unsigned long long pk = ((unsigned long long)key << 32) | (unsigned)j;
        if (pk < best) best = pk;
    }
#pragma unroll
    for (int off = 16; off; off >>= 1) {
        unsigned long long o = __shfl_xor_sync(0xffffffffu, best, off);
        if (o < best) best = o;
    }
    if ((t & 31) == 0) redp[t >> 5] = best;
    __syncthreads();
    if (t == 0) {
        unsigned long long b = redp[0];
#pragma unroll
        for (int w = 1; w < 8; w++) if (redp[w] < b) b = redp[w];
        int id = (int)(b & 0xffffffffu);
        g_ids[row] = id;
        ids_f[row] = (float)id;
    }
}

// e_k[n][c][hw] = codebook[ids[n][hw]][c]
__global__ void ek_kernel(const float* __restrict__ cb, float* __restrict__ ek) {
    size_t i = (size_t)blockIdx.x * 256 + threadIdx.x;
    int hw = (int)(i & 1023);
    int c  = (int)((i >> 10) & 255);
    int n  = (int)(i >> 18);
    int id = g_ids[n * 1024 + hw];
    ek[i] = cb[(size_t)id * 256 + c];
}

// ---------------------------------------------------------------------------
extern "C" void kernel_launch(void* const* d_in, const int* in_sizes, int n_in,
                              void* d_out, int out_size) {
    const float* x   = (const float*)d_in[0];
    const float* ew0 = (const float*)d_in[1];
    const float* ew1 = (const float*)d_in[2];
    const float* ew2 = (const float*)d_in[3];
    const float* cb  = (const float*)d_in[4];
    const float* dw0 = (const float*)d_in[5];
    const float* dw1 = (const float*)d_in[6];
    const float* dw2 = (const float*)d_in[7];
    float* out = (float*)d_out;

    float* bufA = nullptr;
    float* bufB = nullptr;
    cudaGetSymbolAddress((void**)&bufA, g_bufA);
    cudaGetSymbolAddress((void**)&bufB, g_bufB);

    // encoder (single-accumulator (kh,kw,ci) order)
    conv_s2<3, 64, 256, 16, 1, 128, true><<<dim3(128, 32, 4), 128>>>(x, ew0, bufA);
    conv_s2<64, 128, 128, 16, 2, 64, true><<<dim3(32, 32, 8), 128>>>(bufA, ew1, bufB);
    conv_s2<128, 256, 64, 8, 4, 32, false><<<dim3(8, 32, 32), 128>>>(bufB, ew2, out + Z_OFF);

    // VQ
    cb_t_kernel<<<1024, 256>>>(cb);
    cb_norm_kernel<<<4, 256>>>(cb);
    reset_flags_kernel<<<1, 32>>>();
    vq_kernel<<<2048, 128>>>(out + Z_OFF, out + IDS_OFF);
    vq_fix_kernel<<<16384, 256>>>(out + Z_OFF, out + IDS_OFF);
    ek_kernel<<<32768, 256>>>(cb, out + EK_OFF);

    // decoder
    deconv_s2<256, 128, 32, 8, 4, 32, 8, 0><<<dim3(8, 32, 16), 128>>>(out + EK_OFF, dw0, bufB);
    deconv_s2<128, 64, 64, 8, 2, 64, 8, 0><<<dim3(32, 32, 8), 128>>>(bufB, dw1, bufA);
    deconv_s2<64, 3, 128, 3, 1, 128, 8, 1><<<dim3(128, 32, 1), 128>>>(bufA, dw2, out + OUT_OFF);
}